// round 14
// baseline (speedup 1.0000x reference)
#include <cuda_runtime.h>
#include <cuda_bf16.h>
#include <cstdint>
#include <cstddef>

// ---------------- problem constants ----------------
#define B_SZ   256
#define T_SZ   1024
#define I_SZ   128
#define H_SZ   256
#define CLC    4                 // CTAs per cluster (hidden split: 64 h each)
#define GRID_CTAS 128            // 32 clusters x 8 batch rows
#define THREADS2 512             // 16 warps, one pipeline
#define NBC    8                 // batch rows per cluster

// ---------------- recurrent kernel SMEM ----------------
#define SA2 264                              // stride els; 528B = 33*16B odd -> conflict-free ldsm
#define A_BYTES2  (256 * SA2 * 2)            // 135168 (256 gate rows x 256 k, single bf16)
#define MBAR_OFF  (A_BYTES2 + 64)            // 135232
#define SMEM2     (MBAR_OFF + 64)

// ---------------- precompute kernel SMEM ----------------
#define SA3 264
#define PC_A_BYTES (128 * SA3 * 2)           // 67584 (x tile, M=128)
#define PC_B_BYTES (256 * SA3 * 2)           // 135168 (W tile, N=256)
#define SMEM3 (PC_A_BYTES + PC_B_BYTES)      // 202752

// x-projection scratch: xp[t*B + b][g*256 + h], fp32, 1 GiB
__device__ float g_xproj[268435456];
// single-bf16 short-state exchange, h-pairs packed in u32: [buf][b][h/2]
__device__ uint32_t g_short_pack[2][B_SZ * (H_SZ / 2)];
// pre-split, transposed x-weights: [gate][h=256][k=128] packed (hi | lo<<16)
__device__ uint32_t g_wxt[4][256 * 128];

// ---------------- helpers ----------------
__device__ __forceinline__ uint32_t smem_u32(const void* p) {
    uint32_t a;
    asm("{ .reg .u64 t; cvta.to.shared.u64 t, %1; cvt.u32.u64 %0, t; }" : "=r"(a) : "l"(p));
    return a;
}
__device__ __forceinline__ void cluster_sync() {
    asm volatile("barrier.cluster.arrive.aligned;" ::: "memory");
    asm volatile("barrier.cluster.wait.aligned;"   ::: "memory");
}
__device__ __forceinline__ void ldsm4(uint32_t* r, uint32_t addr) {
    asm volatile("ldmatrix.sync.aligned.m8n8.x4.shared.b16 {%0,%1,%2,%3}, [%4];"
                 : "=r"(r[0]), "=r"(r[1]), "=r"(r[2]), "=r"(r[3]) : "r"(addr));
}
__device__ __forceinline__ void mma16816(float* d, const uint32_t* a, const uint32_t* b) {
    asm volatile("mma.sync.aligned.m16n8k16.row.col.f32.bf16.bf16.f32 "
                 "{%0,%1,%2,%3}, {%4,%5,%6,%7}, {%8,%9}, {%0,%1,%2,%3};"
                 : "+f"(d[0]), "+f"(d[1]), "+f"(d[2]), "+f"(d[3])
                 : "r"(a[0]), "r"(a[1]), "r"(a[2]), "r"(a[3]), "r"(b[0]), "r"(b[1]));
}
__device__ __forceinline__ void mbar_init(uint32_t mbar, uint32_t cnt) {
    asm volatile("mbarrier.init.shared.b64 [%0], %1;" :: "r"(mbar), "r"(cnt) : "memory");
}
// release.cluster arrive on peer `rank`'s mbarrier. Preceded by __syncthreads,
// so the release is cumulative over the whole CTA's prior global stores.
__device__ __forceinline__ void mbar_arrive_release_cluster(uint32_t local_mbar, uint32_t rank) {
    asm volatile("{\n\t.reg .b32 ra;\n\t"
                 "mapa.shared::cluster.u32 ra, %0, %1;\n\t"
                 "mbarrier.arrive.release.cluster.shared::cluster.b64 _, [ra];\n\t}"
                 :: "r"(local_mbar), "r"(rank) : "memory");
}
__device__ __forceinline__ void mbar_wait_parity(uint32_t mbar, uint32_t parity) {
    asm volatile("{\n\t.reg .pred P1;\n\t"
                 "WAIT_LOOP_%=:\n\t"
                 "mbarrier.try_wait.parity.acquire.cluster.shared::cta.b64 P1, [%0], %1, 0x989680;\n\t"
                 "@P1 bra.uni WAIT_DONE_%=;\n\t"
                 "bra.uni WAIT_LOOP_%=;\n\t"
                 "WAIT_DONE_%=:\n\t}" :: "r"(mbar), "r"(parity) : "memory");
}
__device__ __forceinline__ float tanhap(float x) {
    float y; asm("tanh.approx.f32 %0, %1;" : "=f"(y) : "f"(x)); return y;
}
__device__ __forceinline__ float sigap(float x) {
    return fmaf(0.5f, tanhap(0.5f * x), 0.5f);
}
__device__ __forceinline__ void split_bf16(float v, __nv_bfloat16& hi, __nv_bfloat16& lo) {
    hi = __float2bfloat16_rn(v);
    lo = __float2bfloat16_rn(v - __bfloat162float(hi));
}

// ================= wsplit: Wx -> split/transposed packed global =================
__global__ void __launch_bounds__(256)
wsplit_kernel(const float* __restrict__ Wf_x, const float* __restrict__ Wip_x,
              const float* __restrict__ Wit_x, const float* __restrict__ Wo_x)
{
    const int g = blockIdx.x >> 5;
    const int chunk = blockIdx.x & 31;
    const float* W = (g == 0) ? Wf_x : (g == 1) ? Wip_x : (g == 2) ? Wit_x : Wo_x;
    const int i = chunk * 1024 + threadIdx.x * 4;
    #pragma unroll
    for (int q = 0; q < 4; q++) {
        const int n = (i + q) >> 7, k = (i + q) & 127;
        float v = W[(size_t)k * H_SZ + n];
        __nv_bfloat16 hi, lo;
        split_bf16(v, hi, lo);
        g_wxt[g][i + q] = (uint32_t)__bfloat16_as_ushort(hi) |
                          ((uint32_t)__bfloat16_as_ushort(lo) << 16);
    }
}

// ================= precompute: xp = x @ Wx (3-term accurate) =================
__global__ void __launch_bounds__(256, 1)
xproj_kernel(const float* __restrict__ x)
{
    extern __shared__ char smem[];
    __nv_bfloat16* Ax = (__nv_bfloat16*)smem;                  // [128][264] hi|lo
    __nv_bfloat16* Bw = (__nv_bfloat16*)(smem + PC_A_BYTES);   // [256][264] hi|lo

    const int tid = threadIdx.x;
    const int w   = tid >> 5;
    const int l   = tid & 31;
    const int t   = blockIdx.x >> 1;
    const int bh  = (blockIdx.x & 1) * 128;
    const int g   = blockIdx.y;

    {
        const int r    = tid >> 1;
        const int half = (tid & 1) * 64;
        const float* xr = x + ((size_t)(bh + r) * T_SZ + t) * I_SZ + half;
        #pragma unroll 4
        for (int q = 0; q < 64; q++) {
            __nv_bfloat16 hi, lo;
            split_bf16(xr[q], hi, lo);
            Ax[r * SA3 + half + q]       = hi;
            Ax[r * SA3 + 128 + half + q] = lo;
        }
    }
    {
        const uint32_t* src = g_wxt[g] + (size_t)tid * 128;
        #pragma unroll 4
        for (int q = 0; q < 128; q += 2) {
            uint32_t u0 = __ldcg(src + q), u1 = __ldcg(src + q + 1);
            *(uint32_t*)&Bw[tid * SA3 + q]       = (u0 & 0xffffu) | (u1 << 16);
            *(uint32_t*)&Bw[tid * SA3 + 128 + q] = (u0 >> 16) | (u1 & 0xffff0000u);
        }
    }
    __syncthreads();

    const uint32_t a_lane = smem_u32(Ax) +
        (uint32_t)(((16 * w + (l & 7) + 8 * ((l >> 3) & 1)) * SA3 + 8 * (l >> 4)) * 2);
    const uint32_t b_lane = smem_u32(Bw) +
        (uint32_t)((((l & 7) + 8 * (l >> 4)) * SA3 + 8 * ((l >> 3) & 1)) * 2);

    float acc[32][4];
    #pragma unroll
    for (int i = 0; i < 32; i++)
        #pragma unroll
        for (int j = 0; j < 4; j++) acc[i][j] = 0.0f;

    #pragma unroll 1
    for (int kc = 0; kc < 8; kc++) {
        uint32_t ah[4], al[4];
        ldsm4(ah, a_lane + kc * 32);
        ldsm4(al, a_lane + 256 + kc * 32);
        #pragma unroll
        for (int nt = 0; nt < 16; nt++) {
            uint32_t bh4[4], bl4[4];
            uint32_t ba = b_lane + (uint32_t)(nt * 16 * SA3 * 2) + kc * 32;
            ldsm4(bh4, ba);
            ldsm4(bl4, ba + 256);
            mma16816(acc[2 * nt],     ah, bh4 + 0);
            mma16816(acc[2 * nt + 1], ah, bh4 + 2);
            mma16816(acc[2 * nt],     al, bh4 + 0);
            mma16816(acc[2 * nt + 1], al, bh4 + 2);
            mma16816(acc[2 * nt],     ah, bl4 + 0);
            mma16816(acc[2 * nt + 1], ah, bl4 + 2);
        }
    }

    {
        const size_t row0 = (size_t)t * B_SZ + bh + 16 * w + (l >> 2);
        const int    cb   = g * 256 + (l & 3) * 2;
        #pragma unroll
        for (int nt = 0; nt < 16; nt++) {
            *(float2*)&g_xproj[row0 * 1024 + cb + nt * 16]           = make_float2(acc[2*nt][0], acc[2*nt][1]);
            *(float2*)&g_xproj[(row0 + 8) * 1024 + cb + nt * 16]     = make_float2(acc[2*nt][2], acc[2*nt][3]);
            *(float2*)&g_xproj[row0 * 1024 + cb + nt * 16 + 8]       = make_float2(acc[2*nt+1][0], acc[2*nt+1][1]);
            *(float2*)&g_xproj[(row0 + 8) * 1024 + cb + nt * 16 + 8] = make_float2(acc[2*nt+1][2], acc[2*nt+1][3]);
        }
    }
}

// ================= recurrent kernel: cluster=4, A-frags resident, direct-L2 B =================
__global__ void __launch_bounds__(THREADS2, 1) __cluster_dims__(CLC, 1, 1)
lstm_rec_kernel(const float* __restrict__ Wf_h,  const float* __restrict__ bf,
                const float* __restrict__ Wip_h, const float* __restrict__ bip,
                const float* __restrict__ Wit_h, const float* __restrict__ bit_,
                const float* __restrict__ Wo_h,  const float* __restrict__ bo,
                float* __restrict__ out)
{
    extern __shared__ char smem[];
    __nv_bfloat16* As = (__nv_bfloat16*)smem;
    const uint32_t sb = smem_u32(smem);

    const int tid = threadIdx.x;
    const int w   = tid >> 5;                // M-tile: gate rows 16w..16w+15
    const int l   = tid & 31;
    const int cc  = blockIdx.x & (CLC - 1);  // hidden-slice owner (64 h)
    const int grp = blockIdx.x >> 2;         // 32 clusters
    const int b0  = grp * NBC;

    if (tid == 0) mbar_init(sb + MBAR_OFF, CLC);

    // ---- stage A (short-part weights, K=256, SINGLE bf16) ----
    {
        const int r  = tid >> 1;             // 0..255 : row = 4*h_local + gate
        const int kh = (tid & 1) * 128;
        const int g  = r & 3;
        const int hs = 64 * cc + (r >> 2);
        const float* Wh = (g == 0) ? Wf_h : (g == 1) ? Wip_h : (g == 2) ? Wit_h : Wo_h;
        #pragma unroll 4
        for (int k = kh; k < kh + 128; k++)
            As[r * SA2 + k] = __float2bfloat16_rn(Wh[(size_t)k * H_SZ + hs]);
    }
    // ---- zero step-0 short buffer (own slice: 8 b x 32 u32 h-pairs) ----
    {
        const int rz = tid >> 6, pz = tid & 63;
        if (pz < 32)
            __stcg(&g_short_pack[0][(size_t)(b0 + rz) * 128 + 32 * cc + pz], 0u);
    }
    __syncthreads();

    // ---- A frags into registers (once) ----
    uint32_t ahf[16][4];
    {
        const uint32_t a_lane = sb +
            (uint32_t)(((16 * w + (l & 7) + 8 * ((l >> 3) & 1)) * SA2 + 8 * (l >> 4)) * 2);
        #pragma unroll
        for (int kc = 0; kc < 16; kc++) ldsm4(ahf[kc], a_lane + (uint32_t)kc * 32);
    }

    const uint32_t mbar = sb + MBAR_OFF;

    // ---- direct B-fragment source: lane l covers batch row b0+(l>>2), col group l&3 ----
    const uint32_t boff = (uint32_t)(b0 + (l >> 2)) * 128 + (l & 3);

    // ---- epilogue mapping: 1 cell per lane: h_loc = l>>3, bq = l&7 ----
    const int h_loc = l >> 3;
    const int bq    = l & 7;
    const int hg    = 64 * cc + 4 * w + h_loc;
    const float biasv[4] = {bf[hg], bip[hg], bit_[hg], bo[hg]};
    float longv = 0.0f;

    __threadfence();
    __syncthreads();
    cluster_sync();

    #pragma unroll 1
    for (int t = 0; t < T_SZ; t++) {
        const int cur = t & 1;
        const int nxt = cur ^ 1;

        // prefetch x-projection (issued before the wait)
        float xpv[4];
        {
            const float* xr = g_xproj + ((size_t)t * B_SZ + b0 + bq) * 1024 + hg;
            #pragma unroll
            for (int g = 0; g < 4; g++) xpv[g] = __ldcg(xr + g * 256);
        }

        // wait for all 4 CTAs' step-t short state
        if (t > 0) mbar_wait_parity(mbar, (t - 1) & 1);

        // ===== load B fragments directly from L2 exchange (32 independent LDGs) =====
        const uint32_t* bsrc = g_short_pack[cur] + boff;
        uint32_t bfr[32];
        #pragma unroll
        for (int kc = 0; kc < 16; kc++) {
            bfr[2 * kc]     = __ldcg(bsrc + 8 * kc);
            bfr[2 * kc + 1] = __ldcg(bsrc + 8 * kc + 4);
        }

        // ===== GEMM: M=16 (this warp), N=8, K=256, single term, 2 chains =====
        float acc_e[4] = {0.f, 0.f, 0.f, 0.f};
        float acc_o[4] = {0.f, 0.f, 0.f, 0.f};
        #pragma unroll
        for (int kc = 0; kc < 16; kc += 2) {
            mma16816(acc_e, ahf[kc],     bfr + 2 * kc);
            mma16816(acc_o, ahf[kc + 1], bfr + 2 * (kc + 1));
        }
        const float s0 = acc_e[0] + acc_o[0];
        const float s1 = acc_e[1] + acc_o[1];
        const float s2 = acc_e[2] + acc_o[2];
        const float s3 = acc_e[3] + acc_o[3];

        // ===== shfl-gather the 4 gate values for this lane's (h_loc, bq) =====
        float z[4];
        #pragma unroll
        for (int g = 0; g < 4; g++) {
            const int row  = 4 * h_loc + g;
            const int srcl = ((row & 7) << 2) | (bq >> 1);
            float t0 = __shfl_sync(0xffffffffu, s0, srcl);
            float t1 = __shfl_sync(0xffffffffu, s1, srcl);
            float t2 = __shfl_sync(0xffffffffu, s2, srcl);
            float t3 = __shfl_sync(0xffffffffu, s3, srcl);
            float lo = (bq & 1) ? t1 : t0;
            float hi = (bq & 1) ? t3 : t2;
            z[g] = (h_loc < 2) ? lo : hi;
        }

        // ===== in-register epilogue =====
        {
            #pragma unroll
            for (int g = 0; g < 4; g++) z[g] += xpv[g] + biasv[g];
            float f  = sigap(z[0]);
            float ip = sigap(z[1]);
            float pt = tanhap(z[2]);
            longv = f * longv + ip * pt;
            float o  = sigap(z[3]);
            float ns = tanhap(longv) * o;

            // pack h-pairs: lanes l and l^8 hold h and h^1
            uint32_t mybits = (uint32_t)__bfloat16_as_ushort(__float2bfloat16_rn(ns));
            uint32_t other  = __shfl_xor_sync(0xffffffffu, mybits, 8);
            if ((h_loc & 1) == 0) {
                uint32_t pk = mybits | (other << 16);
                __stcg(&g_short_pack[nxt][(size_t)(b0 + bq) * 128 + (hg >> 1)], pk);
            }

            if (t == T_SZ - 1) {
                const int bbg = b0 + bq;
                out[(size_t)bbg * H_SZ + hg]                       = ns;
                out[(size_t)B_SZ * H_SZ + (size_t)bbg * H_SZ + hg] = longv;
            }
        }
        __syncthreads();   // CTA stores complete -> release arrives are cumulative

        // publish: 4 parallel release arrives (one per rank), tids 0-3
        if (tid < CLC && t < T_SZ - 1)
            mbar_arrive_release_cluster(mbar, (uint32_t)tid);
    }
    cluster_sync();  // keep SMEM alive for in-flight remote arrives
}

// ---------------- launch ----------------
extern "C" void kernel_launch(void* const* d_in, const int* in_sizes, int n_in,
                              void* d_out, int out_size)
{
    (void)in_sizes; (void)n_in; (void)out_size;
    const float* x     = (const float*)d_in[0];
    const float* Wf_h  = (const float*)d_in[1];
    const float* Wf_x  = (const float*)d_in[2];
    const float* bf    = (const float*)d_in[3];
    const float* Wip_h = (const float*)d_in[4];
    const float* Wip_x = (const float*)d_in[5];
    const float* bip   = (const float*)d_in[6];
    const float* Wit_h = (const float*)d_in[7];
    const float* Wit_x = (const float*)d_in[8];
    const float* bit_  = (const float*)d_in[9];
    const float* Wo_h  = (const float*)d_in[10];
    const float* Wo_x  = (const float*)d_in[11];
    const float* bo    = (const float*)d_in[12];
    float* out = (float*)d_out;

    cudaFuncSetAttribute(xproj_kernel,
                         cudaFuncAttributeMaxDynamicSharedMemorySize, SMEM3);
    cudaFuncSetAttribute(lstm_rec_kernel,
                         cudaFuncAttributeMaxDynamicSharedMemorySize, SMEM2);

    wsplit_kernel<<<128, 256>>>(Wf_x, Wip_x, Wit_x, Wo_x);

    dim3 pgrid(2048, 4);
    xproj_kernel<<<pgrid, 256, SMEM3>>>(x);

    lstm_rec_kernel<<<GRID_CTAS, THREADS2, SMEM2>>>(
        Wf_h, bf, Wip_h, bip, Wit_h, bit_, Wo_h, bo, out);
}

// round 15
// speedup vs baseline: 1.5065x; 1.5065x over previous
#include <cuda_runtime.h>
#include <cuda_bf16.h>
#include <cstdint>
#include <cstddef>

// ---------------- problem constants ----------------
#define B_SZ   256
#define T_SZ   1024
#define I_SZ   128
#define H_SZ   256
#define CLC    4                 // CTAs per cluster (hidden split: 64 h each)
#define GRID_CTAS 128            // 32 clusters x 8 batch rows
#define THREADS2 512             // 16 warps
#define NBC    8                 // batch rows per cluster

// ---------------- recurrent kernel SMEM ----------------
#define SA2 264                              // stride els; 528B = 33*16B odd -> conflict-free ldsm
#define A_BYTES2  (256 * SA2 * 2)            // 135168 (256 gate rows x 256 k, single bf16)
#define B_OFF2    A_BYTES2
#define BGB       (NBC * SA2 * 2)            // 4224 per ping-pong buffer
#define MBAR_OFF  (B_OFF2 + 2 * BGB + 64)    // 143680 (aligned)
#define SMEM2     (MBAR_OFF + 64)

// ---------------- precompute kernel SMEM ----------------
#define SA3 264
#define PC_A_BYTES (128 * SA3 * 2)           // 67584 (x tile, M=128)
#define PC_B_BYTES (256 * SA3 * 2)           // 135168 (W tile, N=256)
#define SMEM3 (PC_A_BYTES + PC_B_BYTES)      // 202752

// x-projection scratch: xp[t*B + b][g*256 + h], fp32, 1 GiB
__device__ float g_xproj[268435456];
// pre-split, transposed x-weights: [gate][h=256][k=128] packed (hi | lo<<16)
__device__ uint32_t g_wxt[4][256 * 128];

// ---------------- helpers ----------------
__device__ __forceinline__ uint32_t smem_u32(const void* p) {
    uint32_t a;
    asm("{ .reg .u64 t; cvta.to.shared.u64 t, %1; cvt.u32.u64 %0, t; }" : "=r"(a) : "l"(p));
    return a;
}
__device__ __forceinline__ void cluster_sync() {
    asm volatile("barrier.cluster.arrive.aligned;" ::: "memory");
    asm volatile("barrier.cluster.wait.aligned;"   ::: "memory");
}
__device__ __forceinline__ void ldsm4(uint32_t* r, uint32_t addr) {
    asm volatile("ldmatrix.sync.aligned.m8n8.x4.shared.b16 {%0,%1,%2,%3}, [%4];"
                 : "=r"(r[0]), "=r"(r[1]), "=r"(r[2]), "=r"(r[3]) : "r"(addr));
}
__device__ __forceinline__ void ldsm2(uint32_t* r, uint32_t addr) {
    asm volatile("ldmatrix.sync.aligned.m8n8.x2.shared.b16 {%0,%1}, [%2];"
                 : "=r"(r[0]), "=r"(r[1]) : "r"(addr));
}
__device__ __forceinline__ void mma16816(float* d, const uint32_t* a, const uint32_t* b) {
    asm volatile("mma.sync.aligned.m16n8k16.row.col.f32.bf16.bf16.f32 "
                 "{%0,%1,%2,%3}, {%4,%5,%6,%7}, {%8,%9}, {%0,%1,%2,%3};"
                 : "+f"(d[0]), "+f"(d[1]), "+f"(d[2]), "+f"(d[3])
                 : "r"(a[0]), "r"(a[1]), "r"(a[2]), "r"(a[3]), "r"(b[0]), "r"(b[1]));
}
__device__ __forceinline__ void mbar_init(uint32_t mbar, uint32_t cnt) {
    asm volatile("mbarrier.init.shared.b64 [%0], %1;" :: "r"(mbar), "r"(cnt) : "memory");
}
// release.cluster arrive on peer `rank`'s mbarrier; preceded by __syncthreads so
// the release is cumulative over the whole CTA's prior shared::cluster stores.
__device__ __forceinline__ void mbar_arrive_release_cluster(uint32_t local_mbar, uint32_t rank) {
    asm volatile("{\n\t.reg .b32 ra;\n\t"
                 "mapa.shared::cluster.u32 ra, %0, %1;\n\t"
                 "mbarrier.arrive.release.cluster.shared::cluster.b64 _, [ra];\n\t}"
                 :: "r"(local_mbar), "r"(rank) : "memory");
}
__device__ __forceinline__ void mbar_wait_parity(uint32_t mbar, uint32_t parity) {
    asm volatile("{\n\t.reg .pred P1;\n\t"
                 "WAIT_LOOP_%=:\n\t"
                 "mbarrier.try_wait.parity.acquire.cluster.shared::cta.b64 P1, [%0], %1, 0x989680;\n\t"
                 "@P1 bra.uni WAIT_DONE_%=;\n\t"
                 "bra.uni WAIT_LOOP_%=;\n\t"
                 "WAIT_DONE_%=:\n\t}" :: "r"(mbar), "r"(parity) : "memory");
}
// remote SMEM store via mapa (DSMEM push)
__device__ __forceinline__ void st_remote_u32(uint32_t laddr, uint32_t rank, uint32_t val) {
    asm volatile("{\n\t.reg .b32 ra;\n\t"
                 "mapa.shared::cluster.u32 ra, %0, %1;\n\t"
                 "st.shared::cluster.u32 [ra], %2;\n\t}"
                 :: "r"(laddr), "r"(rank), "r"(val) : "memory");
}
__device__ __forceinline__ float tanhap(float x) {
    float y; asm("tanh.approx.f32 %0, %1;" : "=f"(y) : "f"(x)); return y;
}
__device__ __forceinline__ float sigap(float x) {
    return fmaf(0.5f, tanhap(0.5f * x), 0.5f);
}
__device__ __forceinline__ void split_bf16(float v, __nv_bfloat16& hi, __nv_bfloat16& lo) {
    hi = __float2bfloat16_rn(v);
    lo = __float2bfloat16_rn(v - __bfloat162float(hi));
}

// ================= wsplit: Wx -> split/transposed packed global =================
__global__ void __launch_bounds__(256)
wsplit_kernel(const float* __restrict__ Wf_x, const float* __restrict__ Wip_x,
              const float* __restrict__ Wit_x, const float* __restrict__ Wo_x)
{
    const int g = blockIdx.x >> 5;
    const int chunk = blockIdx.x & 31;
    const float* W = (g == 0) ? Wf_x : (g == 1) ? Wip_x : (g == 2) ? Wit_x : Wo_x;
    const int i = chunk * 1024 + threadIdx.x * 4;
    #pragma unroll
    for (int q = 0; q < 4; q++) {
        const int n = (i + q) >> 7, k = (i + q) & 127;
        float v = W[(size_t)k * H_SZ + n];
        __nv_bfloat16 hi, lo;
        split_bf16(v, hi, lo);
        g_wxt[g][i + q] = (uint32_t)__bfloat16_as_ushort(hi) |
                          ((uint32_t)__bfloat16_as_ushort(lo) << 16);
    }
}

// ================= precompute: xp = x @ Wx (3-term accurate) =================
__global__ void __launch_bounds__(256, 1)
xproj_kernel(const float* __restrict__ x)
{
    extern __shared__ char smem[];
    __nv_bfloat16* Ax = (__nv_bfloat16*)smem;                  // [128][264] hi|lo
    __nv_bfloat16* Bw = (__nv_bfloat16*)(smem + PC_A_BYTES);   // [256][264] hi|lo

    const int tid = threadIdx.x;
    const int w   = tid >> 5;
    const int l   = tid & 31;
    const int t   = blockIdx.x >> 1;
    const int bh  = (blockIdx.x & 1) * 128;
    const int g   = blockIdx.y;

    {
        const int r    = tid >> 1;
        const int half = (tid & 1) * 64;
        const float* xr = x + ((size_t)(bh + r) * T_SZ + t) * I_SZ + half;
        #pragma unroll 4
        for (int q = 0; q < 64; q++) {
            __nv_bfloat16 hi, lo;
            split_bf16(xr[q], hi, lo);
            Ax[r * SA3 + half + q]       = hi;
            Ax[r * SA3 + 128 + half + q] = lo;
        }
    }
    {
        const uint32_t* src = g_wxt[g] + (size_t)tid * 128;
        #pragma unroll 4
        for (int q = 0; q < 128; q += 2) {
            uint32_t u0 = __ldcg(src + q), u1 = __ldcg(src + q + 1);
            *(uint32_t*)&Bw[tid * SA3 + q]       = (u0 & 0xffffu) | (u1 << 16);
            *(uint32_t*)&Bw[tid * SA3 + 128 + q] = (u0 >> 16) | (u1 & 0xffff0000u);
        }
    }
    __syncthreads();

    const uint32_t a_lane = smem_u32(Ax) +
        (uint32_t)(((16 * w + (l & 7) + 8 * ((l >> 3) & 1)) * SA3 + 8 * (l >> 4)) * 2);
    const uint32_t b_lane = smem_u32(Bw) +
        (uint32_t)((((l & 7) + 8 * (l >> 4)) * SA3 + 8 * ((l >> 3) & 1)) * 2);

    float acc[32][4];
    #pragma unroll
    for (int i = 0; i < 32; i++)
        #pragma unroll
        for (int j = 0; j < 4; j++) acc[i][j] = 0.0f;

    #pragma unroll 1
    for (int kc = 0; kc < 8; kc++) {
        uint32_t ah[4], al[4];
        ldsm4(ah, a_lane + kc * 32);
        ldsm4(al, a_lane + 256 + kc * 32);
        #pragma unroll
        for (int nt = 0; nt < 16; nt++) {
            uint32_t bh4[4], bl4[4];
            uint32_t ba = b_lane + (uint32_t)(nt * 16 * SA3 * 2) + kc * 32;
            ldsm4(bh4, ba);
            ldsm4(bl4, ba + 256);
            mma16816(acc[2 * nt],     ah, bh4 + 0);
            mma16816(acc[2 * nt + 1], ah, bh4 + 2);
            mma16816(acc[2 * nt],     al, bh4 + 0);
            mma16816(acc[2 * nt + 1], al, bh4 + 2);
            mma16816(acc[2 * nt],     ah, bl4 + 0);
            mma16816(acc[2 * nt + 1], ah, bl4 + 2);
        }
    }

    {
        const size_t row0 = (size_t)t * B_SZ + bh + 16 * w + (l >> 2);
        const int    cb   = g * 256 + (l & 3) * 2;
        #pragma unroll
        for (int nt = 0; nt < 16; nt++) {
            *(float2*)&g_xproj[row0 * 1024 + cb + nt * 16]           = make_float2(acc[2*nt][0], acc[2*nt][1]);
            *(float2*)&g_xproj[(row0 + 8) * 1024 + cb + nt * 16]     = make_float2(acc[2*nt][2], acc[2*nt][3]);
            *(float2*)&g_xproj[row0 * 1024 + cb + nt * 16 + 8]       = make_float2(acc[2*nt+1][0], acc[2*nt+1][1]);
            *(float2*)&g_xproj[(row0 + 8) * 1024 + cb + nt * 16 + 8] = make_float2(acc[2*nt+1][2], acc[2*nt+1][3]);
        }
    }
}

// ================= recurrent kernel: DSMEM push exchange, cluster=4, single-term bf16 =================
__global__ void __launch_bounds__(THREADS2, 1) __cluster_dims__(CLC, 1, 1)
lstm_rec_kernel(const float* __restrict__ Wf_h,  const float* __restrict__ bf,
                const float* __restrict__ Wip_h, const float* __restrict__ bip,
                const float* __restrict__ Wit_h, const float* __restrict__ bit_,
                const float* __restrict__ Wo_h,  const float* __restrict__ bo,
                float* __restrict__ out)
{
    extern __shared__ char smem[];
    __nv_bfloat16* As = (__nv_bfloat16*)smem;
    const uint32_t sb = smem_u32(smem);

    const int tid = threadIdx.x;
    const int w   = tid >> 5;                // M-tile: gate rows 16w..16w+15
    const int l   = tid & 31;
    const int cc  = blockIdx.x & (CLC - 1);  // hidden-slice owner (64 h)
    const int grp = blockIdx.x >> 2;         // 32 clusters
    const int b0  = grp * NBC;

    if (tid == 0) mbar_init(sb + MBAR_OFF, CLC);

    // ---- stage A (short-part weights, K=256, single bf16) ----
    {
        const int r  = tid >> 1;             // 0..255 : row = 4*h_local + gate
        const int kh = (tid & 1) * 128;
        const int g  = r & 3;
        const int hs = 64 * cc + (r >> 2);
        const float* Wh = (g == 0) ? Wf_h : (g == 1) ? Wip_h : (g == 2) ? Wit_h : Wo_h;
        #pragma unroll 4
        for (int k = kh; k < kh + 128; k++)
            As[r * SA2 + k] = __float2bfloat16_rn(Wh[(size_t)k * H_SZ + hs]);
    }
    // ---- zero both B receive buffers (step-0 short state = 0) ----
    for (int i = tid; i < (2 * BGB) / 4; i += THREADS2)
        ((uint32_t*)(smem + B_OFF2))[i] = 0u;
    __syncthreads();

    const uint32_t a_lane = sb +
        (uint32_t)(((16 * w + (l & 7) + 8 * ((l >> 3) & 1)) * SA2 + 8 * (l >> 4)) * 2);
    const uint32_t b_lane0 = sb + B_OFF2 +
        (uint32_t)(((l & 7) * SA2 + ((l >> 3) & 1) * 8) * 2);
    const uint32_t mbar = sb + MBAR_OFF;

    // ---- epilogue mapping: 1 cell per lane: h_loc = l>>3, bq = l&7 ----
    const int h_loc = l >> 3;
    const int bq    = l & 7;
    const int hg    = 64 * cc + 4 * w + h_loc;
    const float biasv[4] = {bf[hg], bip[hg], bit_[hg], bo[hg]};
    float longv = 0.0f;

    // remote push target (element byte offset within a Bs buffer): row bq, h pair at hg
    const uint32_t push_off = (uint32_t)bq * (SA2 * 2) + (uint32_t)hg * 2;

    __syncthreads();
    cluster_sync();   // peers' buffers + mbar initialized before any remote store

    #pragma unroll 1
    for (int t = 0; t < T_SZ; t++) {
        const int cur = t & 1;
        const int nxt = cur ^ 1;

        // prefetch x-projection (issued before the wait)
        float xpv[4];
        {
            const float* xr = g_xproj + ((size_t)t * B_SZ + b0 + bq) * 1024 + hg;
            #pragma unroll
            for (int g = 0; g < 4; g++) xpv[g] = __ldcg(xr + g * 256);
        }

        // wait for all 4 CTAs' step-t pushes (B tile already in local SMEM!)
        if (t > 0) mbar_wait_parity(mbar, (t - 1) & 1);

        // ===== GEMM: M=16 (this warp), N=8, K=256, single term, 2 chains =====
        const uint32_t b_lane = b_lane0 + (uint32_t)cur * BGB;
        float acc_e[4] = {0.f, 0.f, 0.f, 0.f};
        float acc_o[4] = {0.f, 0.f, 0.f, 0.f};
        #pragma unroll
        for (int kc = 0; kc < 16; kc += 2) {
            uint32_t af0[4], af1[4], b0r[2], b1r[2];
            ldsm4(af0, a_lane + (uint32_t)kc * 32);
            ldsm2(b0r, b_lane + (uint32_t)kc * 32);
            ldsm4(af1, a_lane + (uint32_t)(kc + 1) * 32);
            ldsm2(b1r, b_lane + (uint32_t)(kc + 1) * 32);
            mma16816(acc_e, af0, b0r);
            mma16816(acc_o, af1, b1r);
        }
        const float s0 = acc_e[0] + acc_o[0];
        const float s1 = acc_e[1] + acc_o[1];
        const float s2 = acc_e[2] + acc_o[2];
        const float s3 = acc_e[3] + acc_o[3];

        // ===== shfl-gather the 4 gate values for this lane's (h_loc, bq) =====
        float z[4];
        #pragma unroll
        for (int g = 0; g < 4; g++) {
            const int row  = 4 * h_loc + g;
            const int srcl = ((row & 7) << 2) | (bq >> 1);
            float t0 = __shfl_sync(0xffffffffu, s0, srcl);
            float t1 = __shfl_sync(0xffffffffu, s1, srcl);
            float t2 = __shfl_sync(0xffffffffu, s2, srcl);
            float t3 = __shfl_sync(0xffffffffu, s3, srcl);
            float lo = (bq & 1) ? t1 : t0;
            float hi = (bq & 1) ? t3 : t2;
            z[g] = (h_loc < 2) ? lo : hi;
        }

        // ===== in-register epilogue + DSMEM push to all 4 ranks =====
        {
            #pragma unroll
            for (int g = 0; g < 4; g++) z[g] += xpv[g] + biasv[g];
            float f  = sigap(z[0]);
            float ip = sigap(z[1]);
            float pt = tanhap(z[2]);
            longv = f * longv + ip * pt;
            float o  = sigap(z[3]);
            float ns = tanhap(longv) * o;

            // lanes l and l^8 hold h and h^1: compose the bf16 pair once
            uint32_t mybits = (uint32_t)__bfloat16_as_ushort(__float2bfloat16_rn(ns));
            uint32_t other  = __shfl_xor_sync(0xffffffffu, mybits, 8);
            if ((h_loc & 1) == 0) {
                uint32_t pk = mybits | (other << 16);
                uint32_t laddr = sb + B_OFF2 + (uint32_t)nxt * BGB + push_off;
                #pragma unroll
                for (int d = 0; d < CLC; d++)
                    st_remote_u32(laddr, (uint32_t)d, pk);
            }

            if (t == T_SZ - 1) {
                const int bbg = b0 + bq;
                out[(size_t)bbg * H_SZ + hg]                       = ns;
                out[(size_t)B_SZ * H_SZ + (size_t)bbg * H_SZ + hg] = longv;
            }
        }
        __syncthreads();   // CTA's pushes issued -> release arrives are cumulative

        // publish: 4 parallel release arrives (one per rank), tids 0-3
        if (tid < CLC && t < T_SZ - 1)
            mbar_arrive_release_cluster(mbar, (uint32_t)tid);
    }
    cluster_sync();  // keep SMEM alive for in-flight remote ops
}

// ---------------- launch ----------------
extern "C" void kernel_launch(void* const* d_in, const int* in_sizes, int n_in,
                              void* d_out, int out_size)
{
    (void)in_sizes; (void)n_in; (void)out_size;
    const float* x     = (const float*)d_in[0];
    const float* Wf_h  = (const float*)d_in[1];
    const float* Wf_x  = (const float*)d_in[2];
    const float* bf    = (const float*)d_in[3];
    const float* Wip_h = (const float*)d_in[4];
    const float* Wip_x = (const float*)d_in[5];
    const float* bip   = (const float*)d_in[6];
    const float* Wit_h = (const float*)d_in[7];
    const float* Wit_x = (const float*)d_in[8];
    const float* bit_  = (const float*)d_in[9];
    const float* Wo_h  = (const float*)d_in[10];
    const float* Wo_x  = (const float*)d_in[11];
    const float* bo    = (const float*)d_in[12];
    float* out = (float*)d_out;

    cudaFuncSetAttribute(xproj_kernel,
                         cudaFuncAttributeMaxDynamicSharedMemorySize, SMEM3);
    cudaFuncSetAttribute(lstm_rec_kernel,
                         cudaFuncAttributeMaxDynamicSharedMemorySize, SMEM2);

    wsplit_kernel<<<128, 256>>>(Wf_x, Wip_x, Wit_x, Wo_x);

    dim3 pgrid(2048, 4);
    xproj_kernel<<<pgrid, 256, SMEM3>>>(x);

    lstm_rec_kernel<<<GRID_CTAS, THREADS2, SMEM2>>>(
        Wf_h, bf, Wip_h, bip, Wit_h, bit_, Wo_h, bo, out);
}

// round 16
// speedup vs baseline: 1.7141x; 1.1377x over previous
#include <cuda_runtime.h>
#include <cuda_bf16.h>
#include <cstdint>
#include <cstddef>

// ---------------- problem constants ----------------
#define B_SZ   256
#define T_SZ   1024
#define I_SZ   128
#define H_SZ   256
#define CLC    4                 // CTAs per cluster (hidden split: 64 h each)
#define GRID_CTAS 128            // 32 clusters x 8 batch rows
#define THREADS2 512             // 16 warps
#define NBC    8                 // batch rows per cluster

// ---------------- recurrent kernel SMEM ----------------
#define SA2 264                              // stride els; 528B = 33*16B odd -> conflict-free ldsm
#define A_BYTES2  (256 * SA2 * 2)            // 135168 (256 gate rows x 256 k, single bf16)
#define B_OFF2    A_BYTES2
#define BGB       (NBC * SA2 * 2)            // 4224 per ping-pong buffer
#define MBAR_OFF  (B_OFF2 + 2 * BGB + 64)    // aligned
#define SMEM2     (MBAR_OFF + 64)

// ---------------- precompute kernel SMEM ----------------
#define SA3 264
#define PC_A_BYTES (128 * SA3 * 2)           // 67584 (x tile, M=128)
#define PC_B_BYTES (256 * SA3 * 2)           // 135168 (W tile, N=256)
#define SMEM3 (PC_A_BYTES + PC_B_BYTES)      // 202752

// x-projection scratch: xp[t*B + b][g*256 + h], fp32, 1 GiB
__device__ float g_xproj[268435456];
// pre-split, transposed x-weights: [gate][h=256][k=128] packed (hi | lo<<16)
__device__ uint32_t g_wxt[4][256 * 128];

// ---------------- helpers ----------------
__device__ __forceinline__ uint32_t smem_u32(const void* p) {
    uint32_t a;
    asm("{ .reg .u64 t; cvta.to.shared.u64 t, %1; cvt.u32.u64 %0, t; }" : "=r"(a) : "l"(p));
    return a;
}
__device__ __forceinline__ void cluster_sync() {
    asm volatile("barrier.cluster.arrive.aligned;" ::: "memory");
    asm volatile("barrier.cluster.wait.aligned;"   ::: "memory");
}
__device__ __forceinline__ void ldsm4(uint32_t* r, uint32_t addr) {
    asm volatile("ldmatrix.sync.aligned.m8n8.x4.shared.b16 {%0,%1,%2,%3}, [%4];"
                 : "=r"(r[0]), "=r"(r[1]), "=r"(r[2]), "=r"(r[3]) : "r"(addr));
}
__device__ __forceinline__ void mma16816(float* d, const uint32_t* a, const uint32_t* b) {
    asm volatile("mma.sync.aligned.m16n8k16.row.col.f32.bf16.bf16.f32 "
                 "{%0,%1,%2,%3}, {%4,%5,%6,%7}, {%8,%9}, {%0,%1,%2,%3};"
                 : "+f"(d[0]), "+f"(d[1]), "+f"(d[2]), "+f"(d[3])
                 : "r"(a[0]), "r"(a[1]), "r"(a[2]), "r"(a[3]), "r"(b[0]), "r"(b[1]));
}
__device__ __forceinline__ void mbar_init(uint32_t mbar, uint32_t cnt) {
    asm volatile("mbarrier.init.shared.b64 [%0], %1;" :: "r"(mbar), "r"(cnt) : "memory");
}
// release.cluster arrive on peer `rank`'s mbarrier; preceded by __syncthreads so
// the release is cumulative over the whole CTA's prior shared::cluster stores.
__device__ __forceinline__ void mbar_arrive_release_cluster(uint32_t local_mbar, uint32_t rank) {
    asm volatile("{\n\t.reg .b32 ra;\n\t"
                 "mapa.shared::cluster.u32 ra, %0, %1;\n\t"
                 "mbarrier.arrive.release.cluster.shared::cluster.b64 _, [ra];\n\t}"
                 :: "r"(local_mbar), "r"(rank) : "memory");
}
__device__ __forceinline__ void mbar_wait_parity(uint32_t mbar, uint32_t parity) {
    asm volatile("{\n\t.reg .pred P1;\n\t"
                 "WAIT_LOOP_%=:\n\t"
                 "mbarrier.try_wait.parity.acquire.cluster.shared::cta.b64 P1, [%0], %1, 0x989680;\n\t"
                 "@P1 bra.uni WAIT_DONE_%=;\n\t"
                 "bra.uni WAIT_LOOP_%=;\n\t"
                 "WAIT_DONE_%=:\n\t}" :: "r"(mbar), "r"(parity) : "memory");
}
// remote SMEM store via mapa (DSMEM push)
__device__ __forceinline__ void st_remote_u32(uint32_t laddr, uint32_t rank, uint32_t val) {
    asm volatile("{\n\t.reg .b32 ra;\n\t"
                 "mapa.shared::cluster.u32 ra, %0, %1;\n\t"
                 "st.shared::cluster.u32 [ra], %2;\n\t}"
                 :: "r"(laddr), "r"(rank), "r"(val) : "memory");
}
__device__ __forceinline__ float tanhap(float x) {
    float y; asm("tanh.approx.f32 %0, %1;" : "=f"(y) : "f"(x)); return y;
}
__device__ __forceinline__ float sigap(float x) {
    return fmaf(0.5f, tanhap(0.5f * x), 0.5f);
}
__device__ __forceinline__ void split_bf16(float v, __nv_bfloat16& hi, __nv_bfloat16& lo) {
    hi = __float2bfloat16_rn(v);
    lo = __float2bfloat16_rn(v - __bfloat162float(hi));
}

// ================= wsplit: Wx -> split/transposed packed global =================
__global__ void __launch_bounds__(256)
wsplit_kernel(const float* __restrict__ Wf_x, const float* __restrict__ Wip_x,
              const float* __restrict__ Wit_x, const float* __restrict__ Wo_x)
{
    const int g = blockIdx.x >> 5;
    const int chunk = blockIdx.x & 31;
    const float* W = (g == 0) ? Wf_x : (g == 1) ? Wip_x : (g == 2) ? Wit_x : Wo_x;
    const int i = chunk * 1024 + threadIdx.x * 4;
    #pragma unroll
    for (int q = 0; q < 4; q++) {
        const int n = (i + q) >> 7, k = (i + q) & 127;
        float v = W[(size_t)k * H_SZ + n];
        __nv_bfloat16 hi, lo;
        split_bf16(v, hi, lo);
        g_wxt[g][i + q] = (uint32_t)__bfloat16_as_ushort(hi) |
                          ((uint32_t)__bfloat16_as_ushort(lo) << 16);
    }
}

// ================= precompute: xp = x @ Wx (3-term accurate) =================
__global__ void __launch_bounds__(256, 1)
xproj_kernel(const float* __restrict__ x)
{
    extern __shared__ char smem[];
    __nv_bfloat16* Ax = (__nv_bfloat16*)smem;                  // [128][264] hi|lo
    __nv_bfloat16* Bw = (__nv_bfloat16*)(smem + PC_A_BYTES);   // [256][264] hi|lo

    const int tid = threadIdx.x;
    const int w   = tid >> 5;
    const int l   = tid & 31;
    const int t   = blockIdx.x >> 1;
    const int bh  = (blockIdx.x & 1) * 128;
    const int g   = blockIdx.y;

    {
        const int r    = tid >> 1;
        const int half = (tid & 1) * 64;
        const float* xr = x + ((size_t)(bh + r) * T_SZ + t) * I_SZ + half;
        #pragma unroll 4
        for (int q = 0; q < 64; q++) {
            __nv_bfloat16 hi, lo;
            split_bf16(xr[q], hi, lo);
            Ax[r * SA3 + half + q]       = hi;
            Ax[r * SA3 + 128 + half + q] = lo;
        }
    }
    {
        const uint32_t* src = g_wxt[g] + (size_t)tid * 128;
        #pragma unroll 4
        for (int q = 0; q < 128; q += 2) {
            uint32_t u0 = __ldcg(src + q), u1 = __ldcg(src + q + 1);
            *(uint32_t*)&Bw[tid * SA3 + q]       = (u0 & 0xffffu) | (u1 << 16);
            *(uint32_t*)&Bw[tid * SA3 + 128 + q] = (u0 >> 16) | (u1 & 0xffff0000u);
        }
    }
    __syncthreads();

    const uint32_t a_lane = smem_u32(Ax) +
        (uint32_t)(((16 * w + (l & 7) + 8 * ((l >> 3) & 1)) * SA3 + 8 * (l >> 4)) * 2);
    const uint32_t b_lane = smem_u32(Bw) +
        (uint32_t)((((l & 7) + 8 * (l >> 4)) * SA3 + 8 * ((l >> 3) & 1)) * 2);

    float acc[32][4];
    #pragma unroll
    for (int i = 0; i < 32; i++)
        #pragma unroll
        for (int j = 0; j < 4; j++) acc[i][j] = 0.0f;

    #pragma unroll 1
    for (int kc = 0; kc < 8; kc++) {
        uint32_t ah[4], al[4];
        ldsm4(ah, a_lane + kc * 32);
        ldsm4(al, a_lane + 256 + kc * 32);
        #pragma unroll
        for (int nt = 0; nt < 16; nt++) {
            uint32_t bh4[4], bl4[4];
            uint32_t ba = b_lane + (uint32_t)(nt * 16 * SA3 * 2) + kc * 32;
            ldsm4(bh4, ba);
            ldsm4(bl4, ba + 256);
            mma16816(acc[2 * nt],     ah, bh4 + 0);
            mma16816(acc[2 * nt + 1], ah, bh4 + 2);
            mma16816(acc[2 * nt],     al, bh4 + 0);
            mma16816(acc[2 * nt + 1], al, bh4 + 2);
            mma16816(acc[2 * nt],     ah, bl4 + 0);
            mma16816(acc[2 * nt + 1], ah, bl4 + 2);
        }
    }

    {
        const size_t row0 = (size_t)t * B_SZ + bh + 16 * w + (l >> 2);
        const int    cb   = g * 256 + (l & 3) * 2;
        #pragma unroll
        for (int nt = 0; nt < 16; nt++) {
            *(float2*)&g_xproj[row0 * 1024 + cb + nt * 16]           = make_float2(acc[2*nt][0], acc[2*nt][1]);
            *(float2*)&g_xproj[(row0 + 8) * 1024 + cb + nt * 16]     = make_float2(acc[2*nt][2], acc[2*nt][3]);
            *(float2*)&g_xproj[row0 * 1024 + cb + nt * 16 + 8]       = make_float2(acc[2*nt+1][0], acc[2*nt+1][1]);
            *(float2*)&g_xproj[(row0 + 8) * 1024 + cb + nt * 16 + 8] = make_float2(acc[2*nt+1][2], acc[2*nt+1][3]);
        }
    }
}

// ================= recurrent kernel: DSMEM push, A-frags resident, ldsm4 B =================
__global__ void __launch_bounds__(THREADS2, 1) __cluster_dims__(CLC, 1, 1)
lstm_rec_kernel(const float* __restrict__ Wf_h,  const float* __restrict__ bf,
                const float* __restrict__ Wip_h, const float* __restrict__ bip,
                const float* __restrict__ Wit_h, const float* __restrict__ bit_,
                const float* __restrict__ Wo_h,  const float* __restrict__ bo,
                float* __restrict__ out)
{
    extern __shared__ char smem[];
    __nv_bfloat16* As = (__nv_bfloat16*)smem;
    const uint32_t sb = smem_u32(smem);

    const int tid = threadIdx.x;
    const int w   = tid >> 5;                // M-tile: gate rows 16w..16w+15
    const int l   = tid & 31;
    const int cc  = blockIdx.x & (CLC - 1);  // hidden-slice owner (64 h)
    const int grp = blockIdx.x >> 2;         // 32 clusters
    const int b0  = grp * NBC;

    if (tid == 0) mbar_init(sb + MBAR_OFF, CLC);

    // ---- stage A (short-part weights, K=256, single bf16) ----
    {
        const int r  = tid >> 1;             // 0..255 : row = 4*h_local + gate
        const int kh = (tid & 1) * 128;
        const int g  = r & 3;
        const int hs = 64 * cc + (r >> 2);
        const float* Wh = (g == 0) ? Wf_h : (g == 1) ? Wip_h : (g == 2) ? Wit_h : Wo_h;
        #pragma unroll 4
        for (int k = kh; k < kh + 128; k++)
            As[r * SA2 + k] = __float2bfloat16_rn(Wh[(size_t)k * H_SZ + hs]);
    }
    // ---- zero both B receive buffers (step-0 short state = 0) ----
    for (int i = tid; i < (2 * BGB) / 4; i += THREADS2)
        ((uint32_t*)(smem + B_OFF2))[i] = 0u;
    __syncthreads();

    // ---- A frags into registers (ONCE) ----
    uint32_t ahf[16][4];
    {
        const uint32_t a_lane = sb +
            (uint32_t)(((16 * w + (l & 7) + 8 * ((l >> 3) & 1)) * SA2 + 8 * (l >> 4)) * 2);
        #pragma unroll
        for (int kc = 0; kc < 16; kc++) ldsm4(ahf[kc], a_lane + (uint32_t)kc * 32);
    }

    // B ldsm4 lane base (covers kc pair per ldsm4):
    // lanes 0-7: rows n, col kc*16 ; 8-15: kc*16+8 ; 16-23: (kc+1)*16 ; 24-31: (kc+1)*16+8
    const uint32_t b_lane0 = sb + B_OFF2 +
        (uint32_t)(((l & 7) * SA2 + ((l >> 3) & 1) * 8 + (l >> 4) * 16) * 2);
    const uint32_t mbar = sb + MBAR_OFF;

    // ---- epilogue mapping: 1 cell per lane: h_loc = l>>3, bq = l&7 ----
    const int h_loc = l >> 3;
    const int bq    = l & 7;
    const int hg    = 64 * cc + 4 * w + h_loc;
    const float biasv[4] = {bf[hg], bip[hg], bit_[hg], bo[hg]};
    float longv = 0.0f;

    // remote push target (byte offset within a Bs buffer): row bq, h pair at hg
    const uint32_t push_off = (uint32_t)bq * (SA2 * 2) + (uint32_t)hg * 2;

    __syncthreads();
    cluster_sync();   // peers' buffers + mbar initialized before any remote store

    #pragma unroll 1
    for (int t = 0; t < T_SZ; t++) {
        const int cur = t & 1;
        const int nxt = cur ^ 1;

        // prefetch x-projection (issued before the wait)
        float xpv[4];
        {
            const float* xr = g_xproj + ((size_t)t * B_SZ + b0 + bq) * 1024 + hg;
            #pragma unroll
            for (int g = 0; g < 4; g++) xpv[g] = __ldcg(xr + g * 256);
        }

        // wait for all 4 CTAs' step-t pushes (B tile already resident in SMEM)
        if (t > 0) mbar_wait_parity(mbar, (t - 1) & 1);

        // ===== GEMM: M=16 (this warp), N=8, K=256; A in regs, B via 8 ldsm4 =====
        const uint32_t b_lane = b_lane0 + (uint32_t)cur * BGB;
        float acc_e[4] = {0.f, 0.f, 0.f, 0.f};
        float acc_o[4] = {0.f, 0.f, 0.f, 0.f};
        #pragma unroll
        for (int kc = 0; kc < 16; kc += 2) {
            uint32_t bfr[4];                         // [0,1]=kc frag, [2,3]=kc+1 frag
            ldsm4(bfr, b_lane + (uint32_t)kc * 32);
            mma16816(acc_e, ahf[kc],     bfr + 0);
            mma16816(acc_o, ahf[kc + 1], bfr + 2);
        }
        const float s0 = acc_e[0] + acc_o[0];
        const float s1 = acc_e[1] + acc_o[1];
        const float s2 = acc_e[2] + acc_o[2];
        const float s3 = acc_e[3] + acc_o[3];

        // ===== shfl-gather the 4 gate values for this lane's (h_loc, bq) =====
        float z[4];
        #pragma unroll
        for (int g = 0; g < 4; g++) {
            const int row  = 4 * h_loc + g;
            const int srcl = ((row & 7) << 2) | (bq >> 1);
            float t0 = __shfl_sync(0xffffffffu, s0, srcl);
            float t1 = __shfl_sync(0xffffffffu, s1, srcl);
            float t2 = __shfl_sync(0xffffffffu, s2, srcl);
            float t3 = __shfl_sync(0xffffffffu, s3, srcl);
            float lo = (bq & 1) ? t1 : t0;
            float hi = (bq & 1) ? t3 : t2;
            z[g] = (h_loc < 2) ? lo : hi;
        }

        // ===== in-register epilogue + DSMEM push to all 4 ranks =====
        {
            #pragma unroll
            for (int g = 0; g < 4; g++) z[g] += xpv[g] + biasv[g];
            float f  = sigap(z[0]);
            float ip = sigap(z[1]);
            float pt = tanhap(z[2]);
            longv = f * longv + ip * pt;
            float o  = sigap(z[3]);
            float ns = tanhap(longv) * o;

            // lanes l and l^8 hold h and h^1: compose the bf16 pair once
            uint32_t mybits = (uint32_t)__bfloat16_as_ushort(__float2bfloat16_rn(ns));
            uint32_t other  = __shfl_xor_sync(0xffffffffu, mybits, 8);
            if ((h_loc & 1) == 0) {
                uint32_t pk = mybits | (other << 16);
                uint32_t laddr = sb + B_OFF2 + (uint32_t)nxt * BGB + push_off;
                #pragma unroll
                for (int d = 0; d < CLC; d++)
                    st_remote_u32(laddr, (uint32_t)d, pk);
            }

            if (t == T_SZ - 1) {
                const int bbg = b0 + bq;
                out[(size_t)bbg * H_SZ + hg]                       = ns;
                out[(size_t)B_SZ * H_SZ + (size_t)bbg * H_SZ + hg] = longv;
            }
        }
        __syncthreads();   // CTA's pushes issued -> release arrives are cumulative

        // publish: 4 parallel release arrives (one per rank), tids 0-3
        if (tid < CLC && t < T_SZ - 1)
            mbar_arrive_release_cluster(mbar, (uint32_t)tid);
    }
    cluster_sync();  // keep SMEM alive for in-flight remote ops
}

// ---------------- launch ----------------
extern "C" void kernel_launch(void* const* d_in, const int* in_sizes, int n_in,
                              void* d_out, int out_size)
{
    (void)in_sizes; (void)n_in; (void)out_size;
    const float* x     = (const float*)d_in[0];
    const float* Wf_h  = (const float*)d_in[1];
    const float* Wf_x  = (const float*)d_in[2];
    const float* bf    = (const float*)d_in[3];
    const float* Wip_h = (const float*)d_in[4];
    const float* Wip_x = (const float*)d_in[5];
    const float* bip   = (const float*)d_in[6];
    const float* Wit_h = (const float*)d_in[7];
    const float* Wit_x = (const float*)d_in[8];
    const float* bit_  = (const float*)d_in[9];
    const float* Wo_h  = (const float*)d_in[10];
    const float* Wo_x  = (const float*)d_in[11];
    const float* bo    = (const float*)d_in[12];
    float* out = (float*)d_out;

    cudaFuncSetAttribute(xproj_kernel,
                         cudaFuncAttributeMaxDynamicSharedMemorySize, SMEM3);
    cudaFuncSetAttribute(lstm_rec_kernel,
                         cudaFuncAttributeMaxDynamicSharedMemorySize, SMEM2);

    wsplit_kernel<<<128, 256>>>(Wf_x, Wip_x, Wit_x, Wo_x);

    dim3 pgrid(2048, 4);
    xproj_kernel<<<pgrid, 256, SMEM3>>>(x);

    lstm_rec_kernel<<<GRID_CTAS, THREADS2, SMEM2>>>(
        Wf_h, bf, Wip_h, bip, Wit_h, bit_, Wo_h, bo, out);
}